// round 13
// baseline (speedup 1.0000x reference)
#include <cuda_runtime.h>
#include <cuda_fp16.h>
#include <cstdint>

// ----------------------------------------------------------------------------
// TensorProductWithScalarComponents — mma.sync fp16 HMMA (Round 11)
//
// R11 = R10 (fused, 2 m-tiles/warp + 2-way N split, sync LDG->STS staging)
//     + software-pipelined B staging: chunk u+1 is LDG'd to registers after
//       the k=0 mma group and STS'd after k=2, hiding L2 latency behind mma
//       issue instead of exposing it between barriers. One barrier per u kept.
// ----------------------------------------------------------------------------

#define NS       100000
#define TN       128      // samples per CTA (4 m-groups x 32)
#define NTHREADS 256
#define XS       130      // padded x-tile stride (halfs)

// Folded weights, fp16, fragment-packed per 64-wide u-chunk
__device__ __half g_C0[128 * 64 * 128];  // 2 MB
__device__ __half g_C1[64 * 64 * 64];    // 512 KB
__device__ __half g_C2[32 * 64 * 32];    // 128 KB

__device__ __forceinline__ uint32_t hmul2u(uint32_t a, uint32_t b) {
    __half2 r = __hmul2(*(__half2*)&a, *(__half2*)&b);
    return *(uint32_t*)&r;
}

__device__ __forceinline__ void mma16816(float* c, uint32_t a0, uint32_t a1,
                                         uint32_t a2, uint32_t a3,
                                         uint32_t b0, uint32_t b1) {
    asm volatile(
        "mma.sync.aligned.m16n8k16.row.col.f32.f16.f16.f32 "
        "{%0,%1,%2,%3},{%4,%5,%6,%7},{%8,%9},{%0,%1,%2,%3};"
        : "+f"(c[0]), "+f"(c[1]), "+f"(c[2]), "+f"(c[3])
        : "r"(a0), "r"(a1), "r"(a2), "r"(a3), "r"(b0), "r"(b1));
}

// ---------------------------------------------------------------------------
// Stage 1: C[u,v,w2] = (1/(8m)) * sum_w Wt[uv,w]*Wl[w,w2], fp16, stored in
// mma.m16n8k16 B-fragment order per u-chunk (proven R7-R10).
// ---------------------------------------------------------------------------
template <int M, int BLK>
__global__ void precompute_kernel(const float* __restrict__ Wt,
                                  const float* __restrict__ Wl) {
    __half* C = (BLK == 0) ? g_C0 : (BLK == 1) ? g_C1 : g_C2;
    __shared__ float wt[M];
    const int uv = blockIdx.x;
    const float* wtrow = Wt + (size_t)uv * M;
    for (int w = threadIdx.x; w < M; w += blockDim.x) wt[w] = wtrow[w];
    __syncthreads();

    const int w2 = threadIdx.x;
    float acc = 0.f;
#pragma unroll 4
    for (int w = 0; w < M; ++w) acc = fmaf(wt[w], Wl[w * M + w2], acc);
    acc *= (1.0f / (8.0f * (float)M));

    const int u = uv >> 6, v = uv & 63;
    const uint32_t lane = (uint32_t)(w2 & 7) * 4 + ((v & 7) >> 1);
    const uint32_t slot = (uint32_t)(v & 1) + (((v >> 3) & 1) << 1);
    const uint32_t idx = (uint32_t)u * (64u * M) +
                         (((uint32_t)(v >> 4) * (M / 8) + (w2 >> 3)) * 32u + lane) * 4u + slot;
    C[idx] = __float2half(acc);
}

// ---------------------------------------------------------------------------
// GEMM body. CTA = 128 samples x M outputs for one mc.
// 8 warps = 4 m-groups (32 samples = 2 m-tiles) x 2 n-groups (NT/2 tiles).
// ---------------------------------------------------------------------------
template <int M, int D, int BLK, int XOFF>
__device__ __forceinline__ void mma_body(const float* __restrict__ x,
                                         const float* __restrict__ y,
                                         float* __restrict__ out, int mc) {
    constexpr int NT  = M / 8;        // total n-tiles
    constexpr int NTW = NT / 2;       // n-tiles per warp (8/4/2)
    constexpr int U   = M;            // u-chunks
    constexpr int CH  = 64 * M;       // halfs per B chunk
    constexpr int CPT = CH / 8 / NTHREADS;  // uint4 copies per thread (4/2/1)

    const __half* Cg = (BLK == 0) ? g_C0 : (BLK == 1) ? g_C1 : g_C2;

    extern __shared__ char smem[];
    __half* sx = (__half*)smem;                 // [M][XS] x tile (fp16)
    __half* Bs = (__half*)(smem + M * XS * 2);  // [2][CH] B double buffer

    const int tid  = threadIdx.x;
    const int wid  = tid >> 5;
    const int lane = tid & 31;
    const int mg   = wid >> 1;        // m-group 0..3
    const int ng   = wid & 1;         // n-group 0..1
    const int n0   = blockIdx.x * TN;
    int nrem = NS - n0; if (nrem > TN) nrem = TN;

    const int s1 = mg * 32 + (lane >> 2);   // 4 sample rows (2 m-tiles)
    const int s2 = s1 + 8;
    const int s3 = s1 + 16;
    const int s4 = s1 + 24;

    // ---- preload y in A-fragment positions for 4 rows ----
    uint32_t yv[4][8];
#pragma unroll
    for (int i = 0; i < 4; ++i) {
        const int s = s1 + i * 8;
        const bool valid = s < nrem;
        const float* yr = y + (size_t)(n0 + s) * 64;
#pragma unroll
        for (int k = 0; k < 4; ++k) {
            const int v0 = 16 * k + 2 * (lane & 3);
            float2 p = make_float2(0.f, 0.f), q = make_float2(0.f, 0.f);
            if (valid) {
                p = *(const float2*)(yr + v0);
                q = *(const float2*)(yr + v0 + 8);
            }
            __half2 hp = __floats2half2_rn(p.x, p.y);
            __half2 hq = __floats2half2_rn(q.x, q.y);
            yv[i][2 * k]     = *(uint32_t*)&hp;
            yv[i][2 * k + 1] = *(uint32_t*)&hq;
        }
    }

    // ---- x tile -> SMEM fp16, transposed [u][s] ----
    for (int idx = tid; idx < M * TN; idx += NTHREADS) {
        const int u = idx % M;
        const int s = idx / M;
        float v = 0.f;
        if (s < nrem) v = x[(size_t)(n0 + s) * 480 + XOFF + u * D + mc];
        sx[u * XS + s] = __float2half(v);
    }

    float acc[2][NTW][4];
#pragma unroll
    for (int h = 0; h < 2; ++h)
#pragma unroll
        for (int t = 0; t < NTW; ++t)
#pragma unroll
            for (int j = 0; j < 4; ++j) acc[h][t][j] = 0.f;

    // ---- prologue: stage chunk 0 ----
    {
        const uint4* src = (const uint4*)Cg;
        uint4* dst = (uint4*)Bs;
#pragma unroll
        for (int i = 0; i < CPT; ++i)
            dst[tid + i * NTHREADS] = src[tid + i * NTHREADS];
    }
    __syncthreads();  // chunk 0 + sx visible

    // one k-step of 2xNTW mmas
#define DO_K(k)                                                                \
    {                                                                          \
        const uint32_t a0 = hmul2u(yv[0][2 * (k)],     x1p);                   \
        const uint32_t a1 = hmul2u(yv[1][2 * (k)],     x2p);                   \
        const uint32_t a2 = hmul2u(yv[0][2 * (k) + 1], x1p);                   \
        const uint32_t a3 = hmul2u(yv[1][2 * (k) + 1], x2p);                   \
        const uint32_t c0 = hmul2u(yv[2][2 * (k)],     x3p);                   \
        const uint32_t c1 = hmul2u(yv[3][2 * (k)],     x4p);                   \
        const uint32_t c2 = hmul2u(yv[2][2 * (k) + 1], x3p);                   \
        const uint32_t c3 = hmul2u(yv[3][2 * (k) + 1], x4p);                   \
        _Pragma("unroll")                                                      \
        for (int nt = 0; nt < NTW; ++nt) {                                     \
            const uint2 b = bp[((k) * NT + ng * NTW + nt) * 32];               \
            mma16816(acc[0][nt], a0, a1, a2, a3, b.x, b.y);                    \
            mma16816(acc[1][nt], c0, c1, c2, c3, b.x, b.y);                    \
        }                                                                      \
    }

    // ---- main loop: compute u, prefetch u+1 interleaved ----
    for (int u = 0; u < U; ++u) {
        __half2 h1 = __half2half2(sx[u * XS + s1]);
        __half2 h2 = __half2half2(sx[u * XS + s2]);
        __half2 h3 = __half2half2(sx[u * XS + s3]);
        __half2 h4 = __half2half2(sx[u * XS + s4]);
        const uint32_t x1p = *(uint32_t*)&h1, x2p = *(uint32_t*)&h2;
        const uint32_t x3p = *(uint32_t*)&h3, x4p = *(uint32_t*)&h4;

        const uint2* bp = (const uint2*)(Bs + (u & 1) * CH) + lane;
        const bool hasNext = (u + 1 < U);
        uint4 pre[CPT];

        DO_K(0)
        if (hasNext) {   // LDG chunk u+1 -> regs (latency hidden by k=1,2 mmas)
            const uint4* src = (const uint4*)(Cg + (size_t)(u + 1) * CH);
#pragma unroll
            for (int i = 0; i < CPT; ++i) pre[i] = src[tid + i * NTHREADS];
        }
        DO_K(1)
        DO_K(2)
        if (hasNext) {   // STS chunk u+1 into the other buffer
            uint4* dst = (uint4*)(Bs + ((u + 1) & 1) * CH);
#pragma unroll
            for (int i = 0; i < CPT; ++i) dst[tid + i * NTHREADS] = pre[i];
        }
        DO_K(3)
        __syncthreads();  // chunk u+1 visible; WAR protection for buffers
    }
#undef DO_K

    // ---- store ----
    const int cc = 2 * (lane & 3);
    const int w2b = ng * NTW * 8;
#pragma unroll
    for (int h = 0; h < 2; ++h) {
        const int ra = s1 + h * 16;
        if (ra < nrem) {
            float* orow = out + (size_t)(n0 + ra) * 480 + XOFF + mc;
#pragma unroll
            for (int nt = 0; nt < NTW; ++nt) {
                const int w2 = w2b + nt * 8 + cc;
                orow[(size_t)w2 * D]       = acc[h][nt][0];
                orow[(size_t)(w2 + 1) * D] = acc[h][nt][1];
            }
        }
        const int rb = ra + 8;
        if (rb < nrem) {
            float* orow = out + (size_t)(n0 + rb) * 480 + XOFF + mc;
#pragma unroll
            for (int nt = 0; nt < NTW; ++nt) {
                const int w2 = w2b + nt * 8 + cc;
                orow[(size_t)w2 * D]       = acc[h][nt][2];
                orow[(size_t)(w2 + 1) * D] = acc[h][nt][3];
            }
        }
    }
}

// Fused dispatcher: y=0 -> block0; y=1..3 -> block1 (mc=y-1); y=4..8 -> block2.
__global__ __launch_bounds__(NTHREADS)
void fused_mma_kernel(const float* __restrict__ x,
                      const float* __restrict__ y,
                      float* __restrict__ out) {
    const int by = blockIdx.y;
    if (by == 0)       mma_body<128, 1, 0, 0>(x, y, out, 0);
    else if (by <= 3)  mma_body<64, 3, 1, 128>(x, y, out, by - 1);
    else               mma_body<32, 5, 2, 320>(x, y, out, by - 4);
}

// ---------------------------------------------------------------------------

extern "C" void kernel_launch(void* const* d_in, const int* in_sizes, int n_in,
                              void* d_out, int out_size) {
    // Bind inputs by element count — robust to any metadata ordering.
    const float *x = 0, *y = 0, *Wt0 = 0, *Wt1 = 0, *Wt2 = 0,
                *Wl0 = 0, *Wl1 = 0, *Wl2 = 0;
    for (int i = 0; i < n_in; ++i) {
        const float* p = (const float*)d_in[i];
        switch (in_sizes[i]) {
            case 48000000: x   = p; break;
            case 6400000:  y   = p; break;
            case 1048576:  Wt0 = p; break;
            case 262144:   Wt1 = p; break;
            case 65536:    Wt2 = p; break;
            case 16384:    Wl0 = p; break;
            case 4096:     Wl1 = p; break;
            case 1024:     Wl2 = p; break;
            default: break;
        }
    }
    float* out = (float*)d_out;

    precompute_kernel<128, 0><<<128 * 64, 128>>>(Wt0, Wl0);
    precompute_kernel<64, 1><<<64 * 64, 64>>>(Wt1, Wl1);
    precompute_kernel<32, 2><<<32 * 64, 32>>>(Wt2, Wl2);

    const int ntiles = (NS + TN - 1) / TN;  // 782

    constexpr int SMMAX = (128 * XS + 2 * 64 * 128) * 2;  // 66048 B (block0 path)

    cudaFuncSetAttribute(fused_mma_kernel,
                         cudaFuncAttributeMaxDynamicSharedMemorySize, SMMAX);

    fused_mma_kernel<<<dim3(ntiles, 9), NTHREADS, SMMAX>>>(x, y, out);
}

// round 14
// speedup vs baseline: 1.8127x; 1.8127x over previous
#include <cuda_runtime.h>
#include <cuda_fp16.h>
#include <cstdint>

// ----------------------------------------------------------------------------
// TensorProductWithScalarComponents — mma.sync fp16 HMMA (Round 14)
//
// R14 = R10 (best: fused, 2 m-tiles/warp + 2-way N split, write/sync/compute
//       staging, 128 regs = 2 CTAs/SM) with two zero-register-pressure tweaks:
//  1) pair staging: TWO u-chunks copied per barrier (barriers + exposed-LDG
//     events halved; transient copy regs only, __launch_bounds__(256,2) pins
//     the 2-CTA register budget).
//  2) fragment-pair packing: stage-1 interleaves adjacent n-tiles' B fragments
//     into one uint4 -> 16 LDS.128 instead of 32 LDS.64 per thread per u
//     (same bytes, half the LDS issue slots).
// ----------------------------------------------------------------------------

#define NS       100000
#define TN       128      // samples per CTA (4 m-groups x 32)
#define NTHREADS 256
#define XS       130      // padded x-tile stride (halfs)

// Folded weights, fp16, fragment-pair-packed per 64-wide u-chunk
__device__ __half g_C0[128 * 64 * 128];  // 2 MB
__device__ __half g_C1[64 * 64 * 64];    // 512 KB
__device__ __half g_C2[32 * 64 * 32];    // 128 KB

__device__ __forceinline__ uint32_t hmul2u(uint32_t a, uint32_t b) {
    __half2 r = __hmul2(*(__half2*)&a, *(__half2*)&b);
    return *(uint32_t*)&r;
}

__device__ __forceinline__ void mma16816(float* c, uint32_t a0, uint32_t a1,
                                         uint32_t a2, uint32_t a3,
                                         uint32_t b0, uint32_t b1) {
    asm volatile(
        "mma.sync.aligned.m16n8k16.row.col.f32.f16.f16.f32 "
        "{%0,%1,%2,%3},{%4,%5,%6,%7},{%8,%9},{%0,%1,%2,%3};"
        : "+f"(c[0]), "+f"(c[1]), "+f"(c[2]), "+f"(c[3])
        : "r"(a0), "r"(a1), "r"(a2), "r"(a3), "r"(b0), "r"(b1));
}

// ---------------------------------------------------------------------------
// Stage 1: C[u,v,w2] = (1/(8m)) * sum_w Wt[uv,w]*Wl[w,w2], fp16, stored in
// mma B-fragment order with ADJACENT N-TILES PAIRED into uint4:
//   kstep=v/16, lane=(w2%8)*4+((v%8)/2), slot=(v&1)+2*((v>>3)&1)
//   ntile=w2/8, ntp=ntile/2, q=ntile&1
//   half index = u*64*M + ((kstep*(NT/2)+ntp)*32 + lane)*8 + q*4 + slot
// ---------------------------------------------------------------------------
template <int M, int BLK>
__global__ void precompute_kernel(const float* __restrict__ Wt,
                                  const float* __restrict__ Wl) {
    __half* C = (BLK == 0) ? g_C0 : (BLK == 1) ? g_C1 : g_C2;
    constexpr int NT = M / 8;
    __shared__ float wt[M];
    const int uv = blockIdx.x;
    const float* wtrow = Wt + (size_t)uv * M;
    for (int w = threadIdx.x; w < M; w += blockDim.x) wt[w] = wtrow[w];
    __syncthreads();

    const int w2 = threadIdx.x;
    float acc = 0.f;
#pragma unroll 4
    for (int w = 0; w < M; ++w) acc = fmaf(wt[w], Wl[w * M + w2], acc);
    acc *= (1.0f / (8.0f * (float)M));

    const int u = uv >> 6, v = uv & 63;
    const uint32_t lane = (uint32_t)(w2 & 7) * 4 + ((v & 7) >> 1);
    const uint32_t slot = (uint32_t)(v & 1) + (((v >> 3) & 1) << 1);
    const uint32_t nt   = (uint32_t)(w2 >> 3);
    const uint32_t idx  = (uint32_t)u * (64u * M) +
                          (((uint32_t)(v >> 4) * (NT / 2) + (nt >> 1)) * 32u + lane) * 8u +
                          (nt & 1) * 4u + slot;
    C[idx] = __float2half(acc);
}

// ---------------------------------------------------------------------------
// GEMM body. CTA = 128 samples x M outputs for one mc.
// 8 warps = 4 m-groups (32 samples = 2 m-tiles) x 2 n-groups (NT/2 tiles).
// B staged in PAIRS of u-chunks: copy(2u) -> sync -> compute(2u).
// ---------------------------------------------------------------------------
template <int M, int D, int BLK, int XOFF>
__device__ __forceinline__ void mma_body(const float* __restrict__ x,
                                         const float* __restrict__ y,
                                         float* __restrict__ out, int mc) {
    constexpr int NT   = M / 8;         // total n-tiles
    constexpr int NTW  = NT / 2;        // n-tiles per warp (8/4/2)
    constexpr int NTP  = NTW / 2;       // n-tile PAIRS per warp (4/2/1)
    constexpr int U    = M;             // u-chunks
    constexpr int CH   = 64 * M;        // halfs per B chunk
    constexpr int PCH  = 2 * CH;        // halfs per chunk PAIR
    constexpr int CPT  = PCH / 8 / NTHREADS;  // uint4 copies per thread (8/4/2)

    const __half* Cg = (BLK == 0) ? g_C0 : (BLK == 1) ? g_C1 : g_C2;

    extern __shared__ char smem[];
    __half* sx = (__half*)smem;                 // [M][XS] x tile (fp16)
    __half* Bs = (__half*)(smem + M * XS * 2);  // [2][PCH] B pair double buffer

    const int tid  = threadIdx.x;
    const int wid  = tid >> 5;
    const int lane = tid & 31;
    const int mg   = wid >> 1;        // m-group 0..3
    const int ng   = wid & 1;         // n-group 0..1
    const int n0   = blockIdx.x * TN;
    int nrem = NS - n0; if (nrem > TN) nrem = TN;

    const int s1 = mg * 32 + (lane >> 2);   // 4 sample rows (2 m-tiles)
    const int s2 = s1 + 8;
    const int s3 = s1 + 16;
    const int s4 = s1 + 24;

    // ---- preload y in A-fragment positions for 4 rows ----
    uint32_t yv[4][8];
#pragma unroll
    for (int i = 0; i < 4; ++i) {
        const int s = s1 + i * 8;
        const bool valid = s < nrem;
        const float* yr = y + (size_t)(n0 + s) * 64;
#pragma unroll
        for (int k = 0; k < 4; ++k) {
            const int v0 = 16 * k + 2 * (lane & 3);
            float2 p = make_float2(0.f, 0.f), q = make_float2(0.f, 0.f);
            if (valid) {
                p = *(const float2*)(yr + v0);
                q = *(const float2*)(yr + v0 + 8);
            }
            __half2 hp = __floats2half2_rn(p.x, p.y);
            __half2 hq = __floats2half2_rn(q.x, q.y);
            yv[i][2 * k]     = *(uint32_t*)&hp;
            yv[i][2 * k + 1] = *(uint32_t*)&hq;
        }
    }

    // ---- x tile -> SMEM fp16, transposed [u][s] ----
    for (int idx = tid; idx < M * TN; idx += NTHREADS) {
        const int u = idx % M;
        const int s = idx / M;
        float v = 0.f;
        if (s < nrem) v = x[(size_t)(n0 + s) * 480 + XOFF + u * D + mc];
        sx[u * XS + s] = __float2half(v);
    }

    float acc[2][NTW][4];
#pragma unroll
    for (int h = 0; h < 2; ++h)
#pragma unroll
        for (int t = 0; t < NTW; ++t)
#pragma unroll
            for (int j = 0; j < 4; ++j) acc[h][t][j] = 0.f;

    // one k-step: NTP uint4 loads -> 4 mmas each (2 m-tiles x 2 n-tiles)
#define DO_K(k)                                                                \
    {                                                                          \
        const uint32_t a0 = hmul2u(yv[0][2 * (k)],     x1p);                   \
        const uint32_t a1 = hmul2u(yv[1][2 * (k)],     x2p);                   \
        const uint32_t a2 = hmul2u(yv[0][2 * (k) + 1], x1p);                   \
        const uint32_t a3 = hmul2u(yv[1][2 * (k) + 1], x2p);                   \
        const uint32_t c0 = hmul2u(yv[2][2 * (k)],     x3p);                   \
        const uint32_t c1 = hmul2u(yv[3][2 * (k)],     x4p);                   \
        const uint32_t c2 = hmul2u(yv[2][2 * (k) + 1], x3p);                   \
        const uint32_t c3 = hmul2u(yv[3][2 * (k) + 1], x4p);                   \
        _Pragma("unroll")                                                      \
        for (int ntp = 0; ntp < NTP; ++ntp) {                                  \
            const uint4 b = bp4[((k) * (NT / 2) + ng * NTP + ntp) * 32];       \
            mma16816(acc[0][2 * ntp],     a0, a1, a2, a3, b.x, b.y);           \
            mma16816(acc[1][2 * ntp],     c0, c1, c2, c3, b.x, b.y);           \
            mma16816(acc[0][2 * ntp + 1], a0, a1, a2, a3, b.z, b.w);           \
            mma16816(acc[1][2 * ntp + 1], c0, c1, c2, c3, b.z, b.w);           \
        }                                                                      \
    }

    // ---- main loop over u-chunk PAIRS: copy pair, sync, compute both u ----
    for (int p = 0; p < U / 2; ++p) {
        {
            const uint4* src = (const uint4*)(Cg + (size_t)p * PCH);
            uint4* dst = (uint4*)(Bs + (p & 1) * PCH);
#pragma unroll
            for (int i = 0; i < CPT; ++i)
                dst[tid + i * NTHREADS] = src[tid + i * NTHREADS];
        }
        __syncthreads();  // pair p visible; WAR vs reads of pair p-2 (done before sync p-1)

#pragma unroll
        for (int half = 0; half < 2; ++half) {
            const int u = 2 * p + half;
            __half2 h1 = __half2half2(sx[u * XS + s1]);
            __half2 h2 = __half2half2(sx[u * XS + s2]);
            __half2 h3 = __half2half2(sx[u * XS + s3]);
            __half2 h4 = __half2half2(sx[u * XS + s4]);
            const uint32_t x1p = *(uint32_t*)&h1, x2p = *(uint32_t*)&h2;
            const uint32_t x3p = *(uint32_t*)&h3, x4p = *(uint32_t*)&h4;

            const uint4* bp4 = (const uint4*)(Bs + (p & 1) * PCH + half * CH) + lane;

            DO_K(0) DO_K(1) DO_K(2) DO_K(3)
        }
    }
#undef DO_K

    // ---- store ----
    const int cc = 2 * (lane & 3);
    const int w2b = ng * NTW * 8;
#pragma unroll
    for (int h = 0; h < 2; ++h) {
        const int ra = s1 + h * 16;
        if (ra < nrem) {
            float* orow = out + (size_t)(n0 + ra) * 480 + XOFF + mc;
#pragma unroll
            for (int nt = 0; nt < NTW; ++nt) {
                const int w2 = w2b + nt * 8 + cc;
                orow[(size_t)w2 * D]       = acc[h][nt][0];
                orow[(size_t)(w2 + 1) * D] = acc[h][nt][1];
            }
        }
        const int rb = ra + 8;
        if (rb < nrem) {
            float* orow = out + (size_t)(n0 + rb) * 480 + XOFF + mc;
#pragma unroll
            for (int nt = 0; nt < NTW; ++nt) {
                const int w2 = w2b + nt * 8 + cc;
                orow[(size_t)w2 * D]       = acc[h][nt][2];
                orow[(size_t)(w2 + 1) * D] = acc[h][nt][3];
            }
        }
    }
}

// Fused dispatcher: y=0 -> block0; y=1..3 -> block1 (mc=y-1); y=4..8 -> block2.
// launch_bounds(256,2) pins the register budget to the 2-CTA/SM cliff (128).
__global__ __launch_bounds__(NTHREADS, 2)
void fused_mma_kernel(const float* __restrict__ x,
                      const float* __restrict__ y,
                      float* __restrict__ out) {
    const int by = blockIdx.y;
    if (by == 0)       mma_body<128, 1, 0, 0>(x, y, out, 0);
    else if (by <= 3)  mma_body<64, 3, 1, 128>(x, y, out, by - 1);
    else               mma_body<32, 5, 2, 320>(x, y, out, by - 4);
}

// ---------------------------------------------------------------------------

extern "C" void kernel_launch(void* const* d_in, const int* in_sizes, int n_in,
                              void* d_out, int out_size) {
    // Bind inputs by element count — robust to any metadata ordering.
    const float *x = 0, *y = 0, *Wt0 = 0, *Wt1 = 0, *Wt2 = 0,
                *Wl0 = 0, *Wl1 = 0, *Wl2 = 0;
    for (int i = 0; i < n_in; ++i) {
        const float* p = (const float*)d_in[i];
        switch (in_sizes[i]) {
            case 48000000: x   = p; break;
            case 6400000:  y   = p; break;
            case 1048576:  Wt0 = p; break;
            case 262144:   Wt1 = p; break;
            case 65536:    Wt2 = p; break;
            case 16384:    Wl0 = p; break;
            case 4096:     Wl1 = p; break;
            case 1024:     Wl2 = p; break;
            default: break;
        }
    }
    float* out = (float*)d_out;

    precompute_kernel<128, 0><<<128 * 64, 128>>>(Wt0, Wl0);
    precompute_kernel<64, 1><<<64 * 64, 64>>>(Wt1, Wl1);
    precompute_kernel<32, 2><<<32 * 64, 32>>>(Wt2, Wl2);

    const int ntiles = (NS + TN - 1) / TN;  // 782

    // block0 path: sx 33280 B + 2 pair-buffers of 32768 B = 98816 B
    constexpr int SMMAX = 128 * XS * 2 + 2 * (2 * 64 * 128) * 2;  // 98816

    cudaFuncSetAttribute(fused_mma_kernel,
                         cudaFuncAttributeMaxDynamicSharedMemorySize, SMMAX);

    fused_mma_kernel<<<dim3(ntiles, 9), NTHREADS, SMMAX>>>(x, y, out);
}

// round 15
// speedup vs baseline: 1.8746x; 1.0341x over previous
#include <cuda_runtime.h>
#include <cuda_fp16.h>
#include <cstdint>

// ----------------------------------------------------------------------------
// TensorProductWithScalarComponents — mma.sync fp16 HMMA (Round 15)
//
// R15 = R14 (pair staging, fragment-pair uint4 B, 2 m-tiles/warp + 2-way N
//       split, fused dispatch, 128 regs / 2 CTAs/SM) with ONE change:
//   B pair staging uses cp.async.ca (L1-ALLOCATING — R8's regression is
//   attributed to .cg's L1 bypass defeating cross-CTA reuse of the shared
//   weight stream, not to async copy itself), issued for pair p+1 right after
//   the barrier publishing pair p, waited at next loop top. Zero register
//   cost -> immune to the 128-reg occupancy cliff that killed R13.
// ----------------------------------------------------------------------------

#define NS       100000
#define TN       128      // samples per CTA (4 m-groups x 32)
#define NTHREADS 256
#define XS       130      // padded x-tile stride (halfs)

// Folded weights, fp16, fragment-pair-packed per 64-wide u-chunk
__device__ __half g_C0[128 * 64 * 128];  // 2 MB
__device__ __half g_C1[64 * 64 * 64];    // 512 KB
__device__ __half g_C2[32 * 64 * 32];    // 128 KB

__device__ __forceinline__ uint32_t hmul2u(uint32_t a, uint32_t b) {
    __half2 r = __hmul2(*(__half2*)&a, *(__half2*)&b);
    return *(uint32_t*)&r;
}

__device__ __forceinline__ void mma16816(float* c, uint32_t a0, uint32_t a1,
                                         uint32_t a2, uint32_t a3,
                                         uint32_t b0, uint32_t b1) {
    asm volatile(
        "mma.sync.aligned.m16n8k16.row.col.f32.f16.f16.f32 "
        "{%0,%1,%2,%3},{%4,%5,%6,%7},{%8,%9},{%0,%1,%2,%3};"
        : "+f"(c[0]), "+f"(c[1]), "+f"(c[2]), "+f"(c[3])
        : "r"(a0), "r"(a1), "r"(a2), "r"(a3), "r"(b0), "r"(b1));
}

__device__ __forceinline__ uint32_t smem_u32(const void* p) {
    uint32_t a;
    asm("{ .reg .u64 t; cvta.to.shared.u64 t, %1; cvt.u32.u64 %0, t; }"
        : "=r"(a) : "l"(p));
    return a;
}

#define CP_ASYNC_CA16(dst_smem, src_gmem) \
    asm volatile("cp.async.ca.shared.global [%0], [%1], 16;" \
                 :: "r"(dst_smem), "l"(src_gmem) : "memory")
#define CP_COMMIT() asm volatile("cp.async.commit_group;" ::: "memory")
#define CP_WAIT0()  asm volatile("cp.async.wait_group 0;" ::: "memory")

// ---------------------------------------------------------------------------
// Stage 1: C[u,v,w2] = (1/(8m)) * sum_w Wt[uv,w]*Wl[w,w2], fp16, stored in
// mma B-fragment order with ADJACENT N-TILES PAIRED into uint4 (R14 layout).
// ---------------------------------------------------------------------------
template <int M, int BLK>
__global__ void precompute_kernel(const float* __restrict__ Wt,
                                  const float* __restrict__ Wl) {
    __half* C = (BLK == 0) ? g_C0 : (BLK == 1) ? g_C1 : g_C2;
    constexpr int NT = M / 8;
    __shared__ float wt[M];
    const int uv = blockIdx.x;
    const float* wtrow = Wt + (size_t)uv * M;
    for (int w = threadIdx.x; w < M; w += blockDim.x) wt[w] = wtrow[w];
    __syncthreads();

    const int w2 = threadIdx.x;
    float acc = 0.f;
#pragma unroll 4
    for (int w = 0; w < M; ++w) acc = fmaf(wt[w], Wl[w * M + w2], acc);
    acc *= (1.0f / (8.0f * (float)M));

    const int u = uv >> 6, v = uv & 63;
    const uint32_t lane = (uint32_t)(w2 & 7) * 4 + ((v & 7) >> 1);
    const uint32_t slot = (uint32_t)(v & 1) + (((v >> 3) & 1) << 1);
    const uint32_t nt   = (uint32_t)(w2 >> 3);
    const uint32_t idx  = (uint32_t)u * (64u * M) +
                          (((uint32_t)(v >> 4) * (NT / 2) + (nt >> 1)) * 32u + lane) * 8u +
                          (nt & 1) * 4u + slot;
    C[idx] = __float2half(acc);
}

// ---------------------------------------------------------------------------
// GEMM body. CTA = 128 samples x M outputs for one mc.
// 8 warps = 4 m-groups (32 samples = 2 m-tiles) x 2 n-groups (NT/2 tiles).
// B staged in PAIRS via cp.async.ca, pipelined one pair ahead.
// ---------------------------------------------------------------------------
template <int M, int D, int BLK, int XOFF>
__device__ __forceinline__ void mma_body(const float* __restrict__ x,
                                         const float* __restrict__ y,
                                         float* __restrict__ out, int mc) {
    constexpr int NT   = M / 8;         // total n-tiles
    constexpr int NTW  = NT / 2;        // n-tiles per warp (8/4/2)
    constexpr int NTP  = NTW / 2;       // n-tile PAIRS per warp (4/2/1)
    constexpr int U    = M;             // u-chunks
    constexpr int CH   = 64 * M;        // halfs per B chunk
    constexpr int PCH  = 2 * CH;        // halfs per chunk PAIR
    constexpr int CPT  = PCH / 8 / NTHREADS;  // cp.async 16B per thread (8/4/2)

    const __half* Cg = (BLK == 0) ? g_C0 : (BLK == 1) ? g_C1 : g_C2;

    extern __shared__ char smem[];
    __half* sx = (__half*)smem;                 // [M][XS] x tile (fp16)
    __half* Bs = (__half*)(smem + M * XS * 2);  // [2][PCH] B pair double buffer
    const uint32_t sBs = smem_u32(Bs);

    const int tid  = threadIdx.x;
    const int wid  = tid >> 5;
    const int lane = tid & 31;
    const int mg   = wid >> 1;        // m-group 0..3
    const int ng   = wid & 1;         // n-group 0..1
    const int n0   = blockIdx.x * TN;
    int nrem = NS - n0; if (nrem > TN) nrem = TN;

    const int s1 = mg * 32 + (lane >> 2);   // 4 sample rows (2 m-tiles)
    const int s2 = s1 + 8;
    const int s3 = s1 + 16;
    const int s4 = s1 + 24;

    // ---- preload y in A-fragment positions for 4 rows ----
    uint32_t yv[4][8];
#pragma unroll
    for (int i = 0; i < 4; ++i) {
        const int s = s1 + i * 8;
        const bool valid = s < nrem;
        const float* yr = y + (size_t)(n0 + s) * 64;
#pragma unroll
        for (int k = 0; k < 4; ++k) {
            const int v0 = 16 * k + 2 * (lane & 3);
            float2 p = make_float2(0.f, 0.f), q = make_float2(0.f, 0.f);
            if (valid) {
                p = *(const float2*)(yr + v0);
                q = *(const float2*)(yr + v0 + 8);
            }
            __half2 hp = __floats2half2_rn(p.x, p.y);
            __half2 hq = __floats2half2_rn(q.x, q.y);
            yv[i][2 * k]     = *(uint32_t*)&hp;
            yv[i][2 * k + 1] = *(uint32_t*)&hq;
        }
    }

    // ---- x tile -> SMEM fp16, transposed [u][s] ----
    for (int idx = tid; idx < M * TN; idx += NTHREADS) {
        const int u = idx % M;
        const int s = idx / M;
        float v = 0.f;
        if (s < nrem) v = x[(size_t)(n0 + s) * 480 + XOFF + u * D + mc];
        sx[u * XS + s] = __float2half(v);
    }

    float acc[2][NTW][4];
#pragma unroll
    for (int h = 0; h < 2; ++h)
#pragma unroll
        for (int t = 0; t < NTW; ++t)
#pragma unroll
            for (int j = 0; j < 4; ++j) acc[h][t][j] = 0.f;

    // ---- prologue: issue async copy of pair 0 ----
    {
        const char* src = (const char*)Cg;
#pragma unroll
        for (int i = 0; i < CPT; ++i) {
            const int o = (tid + i * NTHREADS) * 16;
            CP_ASYNC_CA16(sBs + o, src + o);
        }
        CP_COMMIT();
    }

    // one k-step: NTP uint4 loads -> 4 mmas each (2 m-tiles x 2 n-tiles)
#define DO_K(k)                                                                \
    {                                                                          \
        const uint32_t a0 = hmul2u(yv[0][2 * (k)],     x1p);                   \
        const uint32_t a1 = hmul2u(yv[1][2 * (k)],     x2p);                   \
        const uint32_t a2 = hmul2u(yv[0][2 * (k) + 1], x1p);                   \
        const uint32_t a3 = hmul2u(yv[1][2 * (k) + 1], x2p);                   \
        const uint32_t c0 = hmul2u(yv[2][2 * (k)],     x3p);                   \
        const uint32_t c1 = hmul2u(yv[3][2 * (k)],     x4p);                   \
        const uint32_t c2 = hmul2u(yv[2][2 * (k) + 1], x3p);                   \
        const uint32_t c3 = hmul2u(yv[3][2 * (k) + 1], x4p);                   \
        _Pragma("unroll")                                                      \
        for (int ntp = 0; ntp < NTP; ++ntp) {                                  \
            const uint4 b = bp4[((k) * (NT / 2) + ng * NTP + ntp) * 32];       \
            mma16816(acc[0][2 * ntp],     a0, a1, a2, a3, b.x, b.y);           \
            mma16816(acc[1][2 * ntp],     c0, c1, c2, c3, b.x, b.y);           \
            mma16816(acc[0][2 * ntp + 1], a0, a1, a2, a3, b.z, b.w);           \
            mma16816(acc[1][2 * ntp + 1], c0, c1, c2, c3, b.z, b.w);           \
        }                                                                      \
    }

    // ---- main loop over pairs: wait(p) -> sync -> issue(p+1) -> compute(p) ----
    for (int p = 0; p < U / 2; ++p) {
        CP_WAIT0();
        __syncthreads();  // pair p visible CTA-wide; compute of p-1 fully done
                          // (arrivals) -> WAR-safe to overwrite buffer (p+1)&1

        if (p + 1 < U / 2) {
            const char* src = (const char*)(Cg + (size_t)(p + 1) * PCH);
            const uint32_t dst = sBs + ((p + 1) & 1) * (PCH * 2);
#pragma unroll
            for (int i = 0; i < CPT; ++i) {
                const int o = (tid + i * NTHREADS) * 16;
                CP_ASYNC_CA16(dst + o, src + o);
            }
            CP_COMMIT();
        }

#pragma unroll
        for (int half = 0; half < 2; ++half) {
            const int u = 2 * p + half;
            __half2 h1 = __half2half2(sx[u * XS + s1]);
            __half2 h2 = __half2half2(sx[u * XS + s2]);
            __half2 h3 = __half2half2(sx[u * XS + s3]);
            __half2 h4 = __half2half2(sx[u * XS + s4]);
            const uint32_t x1p = *(uint32_t*)&h1, x2p = *(uint32_t*)&h2;
            const uint32_t x3p = *(uint32_t*)&h3, x4p = *(uint32_t*)&h4;

            const uint4* bp4 = (const uint4*)(Bs + (p & 1) * PCH + half * CH) + lane;

            DO_K(0) DO_K(1) DO_K(2) DO_K(3)
        }
    }
#undef DO_K

    // ---- store ----
    const int cc = 2 * (lane & 3);
    const int w2b = ng * NTW * 8;
#pragma unroll
    for (int h = 0; h < 2; ++h) {
        const int ra = s1 + h * 16;
        if (ra < nrem) {
            float* orow = out + (size_t)(n0 + ra) * 480 + XOFF + mc;
#pragma unroll
            for (int nt = 0; nt < NTW; ++nt) {
                const int w2 = w2b + nt * 8 + cc;
                orow[(size_t)w2 * D]       = acc[h][nt][0];
                orow[(size_t)(w2 + 1) * D] = acc[h][nt][1];
            }
        }
        const int rb = ra + 8;
        if (rb < nrem) {
            float* orow = out + (size_t)(n0 + rb) * 480 + XOFF + mc;
#pragma unroll
            for (int nt = 0; nt < NTW; ++nt) {
                const int w2 = w2b + nt * 8 + cc;
                orow[(size_t)w2 * D]       = acc[h][nt][2];
                orow[(size_t)(w2 + 1) * D] = acc[h][nt][3];
            }
        }
    }
}

// Fused dispatcher: y=0 -> block0; y=1..3 -> block1 (mc=y-1); y=4..8 -> block2.
// launch_bounds(256,2) pins the register budget to the 2-CTA/SM cliff (128).
__global__ __launch_bounds__(NTHREADS, 2)
void fused_mma_kernel(const float* __restrict__ x,
                      const float* __restrict__ y,
                      float* __restrict__ out) {
    const int by = blockIdx.y;
    if (by == 0)       mma_body<128, 1, 0, 0>(x, y, out, 0);
    else if (by <= 3)  mma_body<64, 3, 1, 128>(x, y, out, by - 1);
    else               mma_body<32, 5, 2, 320>(x, y, out, by - 4);
}

// ---------------------------------------------------------------------------

extern "C" void kernel_launch(void* const* d_in, const int* in_sizes, int n_in,
                              void* d_out, int out_size) {
    // Bind inputs by element count — robust to any metadata ordering.
    const float *x = 0, *y = 0, *Wt0 = 0, *Wt1 = 0, *Wt2 = 0,
                *Wl0 = 0, *Wl1 = 0, *Wl2 = 0;
    for (int i = 0; i < n_in; ++i) {
        const float* p = (const float*)d_in[i];
        switch (in_sizes[i]) {
            case 48000000: x   = p; break;
            case 6400000:  y   = p; break;
            case 1048576:  Wt0 = p; break;
            case 262144:   Wt1 = p; break;
            case 65536:    Wt2 = p; break;
            case 16384:    Wl0 = p; break;
            case 4096:     Wl1 = p; break;
            case 1024:     Wl2 = p; break;
            default: break;
        }
    }
    float* out = (float*)d_out;

    precompute_kernel<128, 0><<<128 * 64, 128>>>(Wt0, Wl0);
    precompute_kernel<64, 1><<<64 * 64, 64>>>(Wt1, Wl1);
    precompute_kernel<32, 2><<<32 * 64, 32>>>(Wt2, Wl2);

    const int ntiles = (NS + TN - 1) / TN;  // 782

    // block0 path: sx 33280 B + 2 pair-buffers of 32768 B = 98816 B
    constexpr int SMMAX = 128 * XS * 2 + 2 * (2 * 64 * 128) * 2;  // 98816

    cudaFuncSetAttribute(fused_mma_kernel,
                         cudaFuncAttributeMaxDynamicSharedMemorySize, SMMAX);

    fused_mma_kernel<<<dim3(ntiles, 9), NTHREADS, SMMAX>>>(x, y, out);
}